// round 15
// baseline (speedup 1.0000x reference)
#include <cuda_runtime.h>
#include <cuda_fp16.h>
#include <cuda_bf16.h>
#include <math.h>
#include <stdint.h>

// Problem dims: B=2, T=2048 -> NT=4096 tokens, D=1024, E=8, F=2048, top-2 -> NP=8192 pairs.
#define NT 4096
#define DD 1024
#define EE 8
#define FF 2048
#define NP (NT * 2)

#define BKH 32          // k per stage (halves)
#define NSTG 4
#define A_STG_B 8192    // 128 rows x 32 halves x 2B

// GU: CTA tile 128x64, warp tile 32x32 dual-acc, occ 2
#define GU_B_STG 4096
#define GU_STG (A_STG_B + 2 * GU_B_STG)  // 16384
#define GU_SMEM (NSTG * GU_STG)          // 65536

// DN: CTA tile 128x128, warp tile 64x32, occ 2
#define B_STG_B 8192
#define DN_STG (A_STG_B + B_STG_B)       // 16384
#define DN_SMEM (NSTG * DN_STG)          // 65536

#define KT_GU (DD / BKH)   // 32
#define KT_DN (FF / BKH)   // 64

#define WSZ ((size_t)EE * DD * FF)       // halves per weight tensor (16.78M)
#define CVT_ELEMS 8192                   // elems per convert chunk (32/thread)
#define CVT_BLKS ((int)(WSZ / CVT_ELEMS))// 2048 chunks per tensor
#define RTR_BLKS (NT / 8)                // 512 router blocks (8 tokens each)
#define MT_MAX 72                        // >= sum ceil(M_e/128) (max 71)
#define GU_NT (FF / 64)                  // 32 n-tiles
#define GU_XCV 32                        // convert slots: 32*72 = 2304 >= CVT_BLKS

// ---------------- static scratch ----------------
__device__ int    g_count[EE];           // zero-initialized at load; re-zeroed post-DN
__device__ int    g_arows[EE * NT];
__device__ int    g_crows[EE * NT];
__device__ float  g_pw[NP];
__device__ __half g_Xh [(size_t)NT * DD];
__device__ __half g_Wgh[WSZ];
__device__ __half g_Wuh[WSZ];
__device__ __half g_Wdh[WSZ];
__device__ __half g_Hh [(size_t)NP * FF];      // compact per-expert H rows

// ---------------- helpers ----------------
__device__ __forceinline__ uint32_t smem_u32(const void* p) {
    uint32_t a;
    asm("{ .reg .u64 t; cvta.to.shared.u64 t, %1; cvt.u32.u64 %0, t; }" : "=r"(a) : "l"(p));
    return a;
}
#define CP_ASYNC16(sdst, gsrc) \
    asm volatile("cp.async.cg.shared.global [%0], [%1], 16;" :: "r"(sdst), "l"(gsrc) : "memory")
#define CP_COMMIT() asm volatile("cp.async.commit_group;" ::: "memory")
#define CP_WAIT2()  asm volatile("cp.async.wait_group 2;" ::: "memory")

#define LDMX4(r0, r1, r2, r3, addr) \
    asm volatile("ldmatrix.sync.aligned.m8n8.x4.shared.b16 {%0,%1,%2,%3}, [%4];" \
                 : "=r"(r0), "=r"(r1), "=r"(r2), "=r"(r3) : "r"(addr))
#define LDMX4T(r0, r1, r2, r3, addr) \
    asm volatile("ldmatrix.sync.aligned.m8n8.x4.trans.shared.b16 {%0,%1,%2,%3}, [%4];" \
                 : "=r"(r0), "=r"(r1), "=r"(r2), "=r"(r3) : "r"(addr))

__device__ __forceinline__ void mma_f16(float* c, const uint32_t* a, uint32_t b0, uint32_t b1) {
    asm volatile(
        "mma.sync.aligned.m16n8k16.row.col.f32.f16.f16.f32 "
        "{%0,%1,%2,%3}, {%4,%5,%6,%7}, {%8,%9}, {%0,%1,%2,%3};"
        : "+f"(c[0]), "+f"(c[1]), "+f"(c[2]), "+f"(c[3])
        : "r"(a[0]), "r"(a[1]), "r"(a[2]), "r"(a[3]), "r"(b0), "r"(b1));
}

// A tile smem address: row r (0..127, 64B rows), 16B group cg (0..3), XOR swizzle
__device__ __forceinline__ uint32_t a_smaddr(uint32_t st, int r, int cg) {
    return st + r * 64 + (((uint32_t)cg ^ (((uint32_t)r >> 1) & 3)) << 4);
}
// B tile (128-wide rows): k row (0..31, 256B rows), 16B group ng (0..15)
__device__ __forceinline__ uint32_t b_smaddr(uint32_t st, int k, int ng) {
    return st + k * 256 + (((uint32_t)ng ^ ((uint32_t)k & 7)) << 4);
}
// B tile (64-wide rows): k row (0..31, 128B rows), 16B group ng (0..7)
__device__ __forceinline__ uint32_t b_smaddr64(uint32_t st, int k, int ng) {
    return st + k * 128 + (((uint32_t)ng ^ ((uint32_t)k & 7)) << 4);
}

// convert one 8192-elem chunk (256 threads x 32 elems, 8 LDG.128 in flight)
__device__ __forceinline__ void cvt_chunk(const float* __restrict__ src,
                                          __half* __restrict__ dst,
                                          int chunk, int tid) {
    const size_t base = (size_t)chunk * CVT_ELEMS + (size_t)tid * 32;
    const float4* s = (const float4*)(src + base);
    uint4* d = (uint4*)(dst + base);
    float4 v[8];
    #pragma unroll
    for (int j = 0; j < 8; j++) v[j] = s[j];
    #pragma unroll
    for (int j = 0; j < 4; j++) {
        __half2 h0 = __floats2half2_rn(v[2 * j].x, v[2 * j].y);
        __half2 h1 = __floats2half2_rn(v[2 * j].z, v[2 * j].w);
        __half2 h2 = __floats2half2_rn(v[2 * j + 1].x, v[2 * j + 1].y);
        __half2 h3 = __floats2half2_rn(v[2 * j + 1].z, v[2 * j + 1].w);
        uint4 o;
        o.x = *reinterpret_cast<uint32_t*>(&h0);
        o.y = *reinterpret_cast<uint32_t*>(&h1);
        o.z = *reinterpret_cast<uint32_t*>(&h2);
        o.w = *reinterpret_cast<uint32_t*>(&h3);
        d[j] = o;
    }
}

// flattened m-tile mapping: tile index -> (expert, m0). returns false if idle.
__device__ __forceinline__ bool map_mtile(int ty, int& e_out, int& m0_out, int& M_out) {
    int acc = 0;
    #pragma unroll
    for (int e = 0; e < EE; e++) {
        const int M = g_count[e];
        const int t = (M + 127) >> 7;
        if (ty < acc + t) {
            e_out = e;
            m0_out = (ty - acc) * 128;
            M_out = M;
            return true;
        }
        acc += t;
    }
    return false;
}

// ---------------- prep kernel -------------------------------------------------
// blocks [0, RTR_BLKS):      warp-per-token router (8 tokens/block) + x fp16 + out zero
// blocks [RTR_BLKS, +2*CVT): fp32->fp16 convert slices of Wg / Wu (Wd done in GU)
__global__ void prep_kernel(const float* __restrict__ x,
                            const float* __restrict__ Wr,
                            const float* __restrict__ Wg,
                            const float* __restrict__ Wu,
                            float* __restrict__ out) {
    const int b = blockIdx.x;
    const int tid = threadIdx.x;

    if (b >= RTR_BLKS) {
        const int cb = b - RTR_BLKS;
        if (cb < CVT_BLKS) cvt_chunk(Wg, g_Wgh, cb, tid);
        else               cvt_chunk(Wu, g_Wuh, cb - CVT_BLKS, tid);
        return;
    }

    // ---- router: warp per token, no block syncs ----
    const int wid = tid >> 5, lane = tid & 31;
    const int t = b * 8 + wid;
    const float* xr = x + (size_t)t * DD;

    float acc[EE];
    #pragma unroll
    for (int e = 0; e < EE; e++) acc[e] = 0.f;

    #pragma unroll
    for (int c = 0; c < 8; c++) {
        const int d0 = c * 128 + lane * 4;
        const float4 v = *(const float4*)(xr + d0);
        {
            __half2 h0 = __floats2half2_rn(v.x, v.y);
            __half2 h1 = __floats2half2_rn(v.z, v.w);
            uint2 o;
            o.x = *reinterpret_cast<uint32_t*>(&h0);
            o.y = *reinterpret_cast<uint32_t*>(&h1);
            *(uint2*)(g_Xh + (size_t)t * DD + d0) = o;
            *(float4*)(out + (size_t)t * DD + d0) = make_float4(0.f, 0.f, 0.f, 0.f);
        }
        const float xv[4] = {v.x, v.y, v.z, v.w};
        #pragma unroll
        for (int j = 0; j < 4; j++) {
            const float4 w0 = *(const float4*)(Wr + (size_t)(d0 + j) * EE);
            const float4 w1 = *(const float4*)(Wr + (size_t)(d0 + j) * EE + 4);
            acc[0] = fmaf(xv[j], w0.x, acc[0]);
            acc[1] = fmaf(xv[j], w0.y, acc[1]);
            acc[2] = fmaf(xv[j], w0.z, acc[2]);
            acc[3] = fmaf(xv[j], w0.w, acc[3]);
            acc[4] = fmaf(xv[j], w1.x, acc[4]);
            acc[5] = fmaf(xv[j], w1.y, acc[5]);
            acc[6] = fmaf(xv[j], w1.z, acc[6]);
            acc[7] = fmaf(xv[j], w1.w, acc[7]);
        }
    }
    #pragma unroll
    for (int o = 16; o; o >>= 1) {
        #pragma unroll
        for (int e = 0; e < EE; e++)
            acc[e] += __shfl_xor_sync(0xffffffffu, acc[e], o);
    }

    if (lane == 0) {
        float mx = acc[0];
        #pragma unroll
        for (int e = 1; e < EE; e++) mx = fmaxf(mx, acc[e]);
        float p[EE], se = 0.f;
        #pragma unroll
        for (int e = 0; e < EE; e++) { p[e] = expf(acc[e] - mx); se += p[e]; }
        const float inv = 1.f / se;
        #pragma unroll
        for (int e = 0; e < EE; e++) p[e] *= inv;
        int e0 = 0;
        #pragma unroll
        for (int e = 1; e < EE; e++) if (p[e] > p[e0]) e0 = e;
        int e1 = (e0 == 0) ? 1 : 0;
        #pragma unroll
        for (int e = 0; e < EE; e++) if (e != e0 && p[e] > p[e1]) e1 = e;
        const float z = expf(p[e1] - p[e0]);
        g_pw[2 * t]     = 1.f / (1.f + z);
        g_pw[2 * t + 1] = z / (1.f + z);
        int i0 = atomicAdd(&g_count[e0], 1);
        g_arows[e0 * NT + i0] = t;
        g_crows[e0 * NT + i0] = 2 * t;
        int i1 = atomicAdd(&g_count[e1], 1);
        g_arows[e1 * NT + i1] = t;
        g_crows[e1 * NT + i1] = 2 * t + 1;
    }
}

// expert prefix offset computed inline from g_count
__device__ __forceinline__ int expert_offset(int e) {
    int a = 0;
    #pragma unroll
    for (int i = 0; i < EE; i++) a += (i < e) ? g_count[i] : 0;
    return a;
}

// ---------------- fused gating+up fp16 GEMM (CTA 128x64, occ 2) --------------
// blockIdx.x in [0,32): GEMM n-tile; [32,64): one-shot Wd fp32->fp16 convert CTA.
// blockIdx.y: flattened m-tile index (MT_MAX slots).
__global__ __launch_bounds__(256, 2)
void moe_gu_kernel(const float* __restrict__ Wd) {
    const int tid = threadIdx.x;
    if (blockIdx.x >= GU_NT) {
        const int chunk = (blockIdx.x - GU_NT) + GU_XCV * blockIdx.y;
        if (chunk < CVT_BLKS) cvt_chunk(Wd, g_Wdh, chunk, tid);
        return;
    }

    int e, m0, M;
    if (!map_mtile(blockIdx.y, e, m0, M)) return;
    const int n0 = blockIdx.x * 64;

    extern __shared__ char sm[];
    const uint32_t smb = smem_u32(sm);
    const int wid = tid >> 5, lane = tid & 31;
    const int g = lane >> 2, t4 = lane & 3;
    const int wm = wid & 3, wn = wid >> 2;
    const int lrow = lane & 7, quad = lane >> 3;
    const int frow = ((quad & 1) << 3) + lrow;
    const int kgi = quad >> 1;
    const int ngq = quad >> 1;

    const int* arows = g_arows + e * NT;
    const __half* Bg = g_Wgh + (size_t)e * DD * FF;
    const __half* Bu = g_Wuh + (size_t)e * DD * FF;

    const __half* gA[2]; uint32_t sA[2];
    #pragma unroll
    for (int j = 0; j < 2; j++) {
        const int idx = tid + j * 256;
        const int r = idx >> 2, cg = idx & 3;
        gA[j] = g_Xh + (size_t)arows[min(m0 + r, M - 1)] * DD + cg * 8;
        sA[j] = a_smaddr(smb, r, cg);
    }
    const int b_k = tid >> 3, b_n = tid & 7;
    const __half* gG = Bg + (size_t)b_k * FF + n0 + b_n * 8;
    const __half* gU = Bu + (size_t)b_k * FF + n0 + b_n * 8;
    const uint32_t sG = b_smaddr64(smb + A_STG_B, b_k, b_n);
    const uint32_t sU = b_smaddr64(smb + A_STG_B + GU_B_STG, b_k, b_n);

    #pragma unroll
    for (int s = 0; s < NSTG - 1; s++) {
        const int kof = s * BKH;
        const uint32_t so = s * GU_STG;
        CP_ASYNC16(sA[0] + so, gA[0] + kof);
        CP_ASYNC16(sA[1] + so, gA[1] + kof);
        CP_ASYNC16(sG + so, gG + (size_t)kof * FF);
        CP_ASYNC16(sU + so, gU + (size_t)kof * FF);
        CP_COMMIT();
    }

    float accG[2][4][4], accU[2][4][4];
    #pragma unroll
    for (int i = 0; i < 2; i++)
        #pragma unroll
        for (int j = 0; j < 4; j++)
            #pragma unroll
            for (int q = 0; q < 4; q++) { accG[i][j][q] = 0.f; accU[i][j][q] = 0.f; }

    for (int kt = 0; kt < KT_GU; kt++) {
        CP_WAIT2();
        __syncthreads();
        {
            const int kn = kt + NSTG - 1;
            if (kn < KT_GU) {
                const int kof = kn * BKH;
                const uint32_t so = (kn & (NSTG - 1)) * GU_STG;
                CP_ASYNC16(sA[0] + so, gA[0] + kof);
                CP_ASYNC16(sA[1] + so, gA[1] + kof);
                CP_ASYNC16(sG + so, gG + (size_t)kof * FF);
                CP_ASYNC16(sU + so, gU + (size_t)kof * FF);
            }
            CP_COMMIT();
        }
        const uint32_t stA = smb + (kt & (NSTG - 1)) * GU_STG;
        const uint32_t stG = stA + A_STG_B;
        const uint32_t stU = stG + GU_B_STG;
        #pragma unroll
        for (int kk = 0; kk < 2; kk++) {
            uint32_t af[2][4];
            #pragma unroll
            for (int mf = 0; mf < 2; mf++) {
                const int r = wm * 32 + mf * 16 + frow;
                LDMX4(af[mf][0], af[mf][1], af[mf][2], af[mf][3],
                      a_smaddr(stA, r, kk * 2 + kgi));
            }
            uint32_t bg[2][4], bu[2][4];
            #pragma unroll
            for (int w16 = 0; w16 < 2; w16++) {
                const int k = kk * 16 + ((quad & 1) << 3) + lrow;
                const int ng = wn * 4 + w16 * 2 + ngq;
                LDMX4T(bg[w16][0], bg[w16][1], bg[w16][2], bg[w16][3],
                       b_smaddr64(stG, k, ng));
                LDMX4T(bu[w16][0], bu[w16][1], bu[w16][2], bu[w16][3],
                       b_smaddr64(stU, k, ng));
            }
            #pragma unroll
            for (int nf = 0; nf < 4; nf++) {
                const int w16 = nf >> 1, sl = (nf & 1) * 2;
                #pragma unroll
                for (int mf = 0; mf < 2; mf++) {
                    mma_f16(accG[mf][nf], af[mf], bg[w16][sl], bg[w16][sl + 1]);
                    mma_f16(accU[mf][nf], af[mf], bu[w16][sl], bu[w16][sl + 1]);
                }
            }
        }
    }

    const int hbase = expert_offset(e);
    const int* crows = g_crows + e * NT;
    #pragma unroll
    for (int mf = 0; mf < 2; mf++) {
        const int r_lo = m0 + wm * 32 + mf * 16 + g;
        const int r_hi = r_lo + 8;
        const bool v_lo = r_lo < M, v_hi = r_hi < M;
        const float pw_lo = v_lo ? g_pw[crows[r_lo]] : 0.f;
        const float pw_hi = v_hi ? g_pw[crows[r_hi]] : 0.f;
        __half* h_lo = g_Hh + (size_t)(hbase + (v_lo ? r_lo : 0)) * FF;
        __half* h_hi = g_Hh + (size_t)(hbase + (v_hi ? r_hi : 0)) * FF;
        #pragma unroll
        for (int nf = 0; nf < 4; nf++) {
            const int cc = n0 + wn * 32 + nf * 8 + t4 * 2;
            if (v_lo) {
                const float g0 = accG[mf][nf][0], u0 = accU[mf][nf][0];
                const float g1 = accG[mf][nf][1], u1 = accU[mf][nf][1];
                *(__half2*)(h_lo + cc) = __floats2half2_rn(
                    pw_lo * (g0 / (1.f + __expf(-g0))) * u0,
                    pw_lo * (g1 / (1.f + __expf(-g1))) * u1);
            }
            if (v_hi) {
                const float g0 = accG[mf][nf][2], u0 = accU[mf][nf][2];
                const float g1 = accG[mf][nf][3], u1 = accU[mf][nf][3];
                *(__half2*)(h_hi + cc) = __floats2half2_rn(
                    pw_hi * (g0 / (1.f + __expf(-g0))) * u0,
                    pw_hi * (g1 / (1.f + __expf(-g1))) * u1);
            }
        }
    }
}

// ---------------- down fp16 GEMM (CTA 128x128, occ 2) -------------------------
// blockIdx.y: flattened m-tile index (MT_MAX slots).
__global__ __launch_bounds__(256, 2)
void moe_dn_kernel(float* __restrict__ out) {
    int e, m0, M;
    if (!map_mtile(blockIdx.y, e, m0, M)) return;
    const int n0 = blockIdx.x * 128;

    extern __shared__ char sm[];
    const uint32_t smb = smem_u32(sm);
    const int tid = threadIdx.x;
    const int wid = tid >> 5, lane = tid & 31;
    const int g = lane >> 2, t4 = lane & 3;
    const int wm = wid & 1, wn = wid >> 1;
    const int lrow = lane & 7, quad = lane >> 3;
    const int frow = ((quad & 1) << 3) + lrow;
    const int kgi = quad >> 1;
    const int ngq = quad >> 1;

    const __half* Bd = g_Wdh + (size_t)e * FF * DD;
    const int base_row = expert_offset(e) + m0;

    const __half* gA[2]; uint32_t sA[2];
    #pragma unroll
    for (int j = 0; j < 2; j++) {
        const int idx = tid + j * 256;
        const int r = idx >> 2, cg = idx & 3;
        gA[j] = g_Hh + (size_t)min(base_row + r, NP - 1) * FF + cg * 8;
        sA[j] = a_smaddr(smb, r, cg);
    }
    const __half* gB[2]; uint32_t sB[2];
    #pragma unroll
    for (int j = 0; j < 2; j++) {
        const int idx = tid + j * 256;
        const int k = idx >> 4, ng = idx & 15;
        gB[j] = Bd + (size_t)k * DD + n0 + ng * 8;
        sB[j] = b_smaddr(smb + A_STG_B, k, ng);
    }

    #pragma unroll
    for (int s = 0; s < NSTG - 1; s++) {
        const int kof = s * BKH;
        const uint32_t so = s * DN_STG;
        #pragma unroll
        for (int j = 0; j < 2; j++) {
            CP_ASYNC16(sA[j] + so, gA[j] + kof);
            CP_ASYNC16(sB[j] + so, gB[j] + (size_t)kof * DD);
        }
        CP_COMMIT();
    }

    float acc[4][4][4];
    #pragma unroll
    for (int i = 0; i < 4; i++)
        #pragma unroll
        for (int j = 0; j < 4; j++)
            #pragma unroll
            for (int q = 0; q < 4; q++) acc[i][j][q] = 0.f;

    for (int kt = 0; kt < KT_DN; kt++) {
        CP_WAIT2();
        __syncthreads();
        {
            const int kn = kt + NSTG - 1;
            if (kn < KT_DN) {
                const int kof = kn * BKH;
                const uint32_t so = (kn & (NSTG - 1)) * DN_STG;
                #pragma unroll
                for (int j = 0; j < 2; j++) {
                    CP_ASYNC16(sA[j] + so, gA[j] + kof);
                    CP_ASYNC16(sB[j] + so, gB[j] + (size_t)kof * DD);
                }
            }
            CP_COMMIT();
        }
        const uint32_t stA = smb + (kt & (NSTG - 1)) * DN_STG;
        const uint32_t stB = stA + A_STG_B;
        #pragma unroll
        for (int kk = 0; kk < 2; kk++) {
            uint32_t af[4][4];
            #pragma unroll
            for (int mf = 0; mf < 4; mf++) {
                const int r = wm * 64 + mf * 16 + frow;
                LDMX4(af[mf][0], af[mf][1], af[mf][2], af[mf][3],
                      a_smaddr(stA, r, kk * 2 + kgi));
            }
            uint32_t bb[2][4];
            #pragma unroll
            for (int w16 = 0; w16 < 2; w16++) {
                const int k = kk * 16 + ((quad & 1) << 3) + lrow;
                const int ng = wn * 4 + w16 * 2 + ngq;
                LDMX4T(bb[w16][0], bb[w16][1], bb[w16][2], bb[w16][3],
                       b_smaddr(stB, k, ng));
            }
            #pragma unroll
            for (int nf = 0; nf < 4; nf++) {
                const int w16 = nf >> 1, sl = (nf & 1) * 2;
                #pragma unroll
                for (int mf = 0; mf < 4; mf++)
                    mma_f16(acc[mf][nf], af[mf], bb[w16][sl], bb[w16][sl + 1]);
            }
        }
    }

    const int* crows = g_crows + e * NT;
    #pragma unroll
    for (int mf = 0; mf < 4; mf++) {
        const int r_lo = m0 + wm * 64 + mf * 16 + g;
        const int r_hi = r_lo + 8;
        float* o_lo = (r_lo < M) ? (out + (size_t)(crows[r_lo] >> 1) * DD) : nullptr;
        float* o_hi = (r_hi < M) ? (out + (size_t)(crows[r_hi] >> 1) * DD) : nullptr;
        #pragma unroll
        for (int nf = 0; nf < 4; nf++) {
            const int cc = n0 + wn * 32 + nf * 8 + t4 * 2;
            if (o_lo) {
                atomicAdd(o_lo + cc,     acc[mf][nf][0]);
                atomicAdd(o_lo + cc + 1, acc[mf][nf][1]);
            }
            if (o_hi) {
                atomicAdd(o_hi + cc,     acc[mf][nf][2]);
                atomicAdd(o_hi + cc + 1, acc[mf][nf][3]);
            }
        }
    }
}

// ---------------- launcher ---------------------------------------------------
extern "C" void kernel_launch(void* const* d_in, const int* in_sizes, int n_in,
                              void* d_out, int out_size) {
    const float* x  = (const float*)d_in[0];
    const float* Wr = (const float*)d_in[1];
    const float* Wg = (const float*)d_in[2];
    const float* Wu = (const float*)d_in[3];
    const float* Wd = (const float*)d_in[4];
    float* out = (float*)d_out;

    cudaFuncSetAttribute(moe_gu_kernel, cudaFuncAttributeMaxDynamicSharedMemorySize, GU_SMEM);
    cudaFuncSetAttribute(moe_dn_kernel, cudaFuncAttributeMaxDynamicSharedMemorySize, DN_SMEM);

    // g_count is zero at first call (static zero-init) and re-zeroed after DN,
    // so every invocation starts with zeroed counts (graph-replay safe).
    prep_kernel<<<RTR_BLKS + 2 * CVT_BLKS, 256>>>(x, Wr, Wg, Wu, out);
    moe_gu_kernel<<<dim3(GU_NT + GU_XCV, MT_MAX, 1), 256, GU_SMEM>>>(Wd);
    moe_dn_kernel<<<dim3(DD / 128, MT_MAX, 1), 256, DN_SMEM>>>(out);

    int* cnt;
    cudaGetSymbolAddress((void**)&cnt, g_count);
    cudaMemsetAsync(cnt, 0, EE * sizeof(int));
}

// round 16
// speedup vs baseline: 1.0679x; 1.0679x over previous
#include <cuda_runtime.h>
#include <cuda_fp16.h>
#include <cuda_bf16.h>
#include <math.h>
#include <stdint.h>

// Problem dims: B=2, T=2048 -> NT=4096 tokens, D=1024, E=8, F=2048, top-2 -> NP=8192 pairs.
#define NT 4096
#define DD 1024
#define EE 8
#define FF 2048
#define NP (NT * 2)

#define BKH 32          // k per stage (halves)
#define NSTG 4
#define A_STG_B 8192    // 128 rows x 32 halves x 2B

// GU: CTA tile 128x64, warp tile 32x32 dual-acc, occ 2
#define GU_B_STG 4096
#define GU_STG (A_STG_B + 2 * GU_B_STG)  // 16384
#define GU_SMEM (NSTG * GU_STG)          // 65536

// DN: CTA tile 128x128, warp tile 64x32, occ 2
#define B_STG_B 8192
#define DN_STG (A_STG_B + B_STG_B)       // 16384
#define DN_SMEM (NSTG * DN_STG)          // 65536

#define KT_GU (DD / BKH)   // 32
#define KT_DN (FF / BKH)   // 64

#define WSZ ((size_t)EE * DD * FF)       // halves per weight tensor (16.78M)
#define CVT_BLKS ((int)(WSZ / 4096))     // 4096 chunks of 4096 elems
#define RTR_BLKS (NT / 8)                // 512 router blocks (8 tokens each)
#define GU_NT (FF / 64)                  // 32 n-tiles
#define GU_XCV 16                        // extra x slots for Wd convert (16*32*8 = 4096)

// ---------------- static scratch ----------------
__device__ int    g_count[EE];           // zero-initialized at load; re-zeroed post-DN
__device__ int    g_arows[EE * NT];
__device__ int    g_crows[EE * NT];
__device__ float  g_pw[NP];
__device__ __half g_Xh [(size_t)NT * DD];
__device__ __half g_Wgh[WSZ];
__device__ __half g_Wuh[WSZ];
__device__ __half g_Wdh[WSZ];
__device__ __half g_Hh [(size_t)NP * FF];      // compact per-expert H rows

// ---------------- helpers ----------------
__device__ __forceinline__ uint32_t smem_u32(const void* p) {
    uint32_t a;
    asm("{ .reg .u64 t; cvta.to.shared.u64 t, %1; cvt.u32.u64 %0, t; }" : "=r"(a) : "l"(p));
    return a;
}
#define CP_ASYNC16(sdst, gsrc) \
    asm volatile("cp.async.cg.shared.global [%0], [%1], 16;" :: "r"(sdst), "l"(gsrc) : "memory")
#define CP_COMMIT() asm volatile("cp.async.commit_group;" ::: "memory")
#define CP_WAIT2()  asm volatile("cp.async.wait_group 2;" ::: "memory")

#define LDMX4(r0, r1, r2, r3, addr) \
    asm volatile("ldmatrix.sync.aligned.m8n8.x4.shared.b16 {%0,%1,%2,%3}, [%4];" \
                 : "=r"(r0), "=r"(r1), "=r"(r2), "=r"(r3) : "r"(addr))
#define LDMX4T(r0, r1, r2, r3, addr) \
    asm volatile("ldmatrix.sync.aligned.m8n8.x4.trans.shared.b16 {%0,%1,%2,%3}, [%4];" \
                 : "=r"(r0), "=r"(r1), "=r"(r2), "=r"(r3) : "r"(addr))

__device__ __forceinline__ void mma_f16(float* c, const uint32_t* a, uint32_t b0, uint32_t b1) {
    asm volatile(
        "mma.sync.aligned.m16n8k16.row.col.f32.f16.f16.f32 "
        "{%0,%1,%2,%3}, {%4,%5,%6,%7}, {%8,%9}, {%0,%1,%2,%3};"
        : "+f"(c[0]), "+f"(c[1]), "+f"(c[2]), "+f"(c[3])
        : "r"(a[0]), "r"(a[1]), "r"(a[2]), "r"(a[3]), "r"(b0), "r"(b1));
}

// A tile smem address: row r (0..127, 64B rows), 16B group cg (0..3), XOR swizzle
__device__ __forceinline__ uint32_t a_smaddr(uint32_t st, int r, int cg) {
    return st + r * 64 + (((uint32_t)cg ^ (((uint32_t)r >> 1) & 3)) << 4);
}
// B tile (128-wide rows): k row (0..31, 256B rows), 16B group ng (0..15)
__device__ __forceinline__ uint32_t b_smaddr(uint32_t st, int k, int ng) {
    return st + k * 256 + (((uint32_t)ng ^ ((uint32_t)k & 7)) << 4);
}
// B tile (64-wide rows): k row (0..31, 128B rows), 16B group ng (0..7)
__device__ __forceinline__ uint32_t b_smaddr64(uint32_t st, int k, int ng) {
    return st + k * 128 + (((uint32_t)ng ^ ((uint32_t)k & 7)) << 4);
}

// convert one 4096-elem chunk (256 threads x 16 elems).
// fp32 source is dead after this read -> evict-first (__ldcs) to keep L2 for fp16.
__device__ __forceinline__ void cvt_chunk(const float* __restrict__ src,
                                          __half* __restrict__ dst,
                                          int chunk, int tid) {
    const size_t base = (size_t)chunk * 4096 + (size_t)tid * 16;
    const float4* s = (const float4*)(src + base);
    uint4* d = (uint4*)(dst + base);
    float4 v[4];
    #pragma unroll
    for (int j = 0; j < 4; j++) v[j] = __ldcs(s + j);
    #pragma unroll
    for (int j = 0; j < 2; j++) {
        __half2 h0 = __floats2half2_rn(v[2 * j].x, v[2 * j].y);
        __half2 h1 = __floats2half2_rn(v[2 * j].z, v[2 * j].w);
        __half2 h2 = __floats2half2_rn(v[2 * j + 1].x, v[2 * j + 1].y);
        __half2 h3 = __floats2half2_rn(v[2 * j + 1].z, v[2 * j + 1].w);
        uint4 o;
        o.x = *reinterpret_cast<uint32_t*>(&h0);
        o.y = *reinterpret_cast<uint32_t*>(&h1);
        o.z = *reinterpret_cast<uint32_t*>(&h2);
        o.w = *reinterpret_cast<uint32_t*>(&h3);
        d[j] = o;
    }
}

// ---------------- prep kernel -------------------------------------------------
// blocks [0, RTR_BLKS):      warp-per-token router (8 tokens/block) + x fp16 + out zero
// blocks [RTR_BLKS, +2*CVT): fp32->fp16 convert slices of Wg / Wu (Wd done in GU)
__global__ void prep_kernel(const float* __restrict__ x,
                            const float* __restrict__ Wr,
                            const float* __restrict__ Wg,
                            const float* __restrict__ Wu,
                            float* __restrict__ out) {
    const int b = blockIdx.x;
    const int tid = threadIdx.x;

    if (b >= RTR_BLKS) {
        const int cb = b - RTR_BLKS;
        if (cb < CVT_BLKS) cvt_chunk(Wg, g_Wgh, cb, tid);
        else               cvt_chunk(Wu, g_Wuh, cb - CVT_BLKS, tid);
        return;
    }

    // ---- router: warp per token, no block syncs ----
    const int wid = tid >> 5, lane = tid & 31;
    const int t = b * 8 + wid;
    const float* xr = x + (size_t)t * DD;

    float acc[EE];
    #pragma unroll
    for (int e = 0; e < EE; e++) acc[e] = 0.f;

    #pragma unroll
    for (int c = 0; c < 8; c++) {
        const int d0 = c * 128 + lane * 4;
        const float4 v = *(const float4*)(xr + d0);
        {
            __half2 h0 = __floats2half2_rn(v.x, v.y);
            __half2 h1 = __floats2half2_rn(v.z, v.w);
            uint2 o;
            o.x = *reinterpret_cast<uint32_t*>(&h0);
            o.y = *reinterpret_cast<uint32_t*>(&h1);
            *(uint2*)(g_Xh + (size_t)t * DD + d0) = o;
            *(float4*)(out + (size_t)t * DD + d0) = make_float4(0.f, 0.f, 0.f, 0.f);
        }
        const float xv[4] = {v.x, v.y, v.z, v.w};
        #pragma unroll
        for (int j = 0; j < 4; j++) {
            const float4 w0 = *(const float4*)(Wr + (size_t)(d0 + j) * EE);
            const float4 w1 = *(const float4*)(Wr + (size_t)(d0 + j) * EE + 4);
            acc[0] = fmaf(xv[j], w0.x, acc[0]);
            acc[1] = fmaf(xv[j], w0.y, acc[1]);
            acc[2] = fmaf(xv[j], w0.z, acc[2]);
            acc[3] = fmaf(xv[j], w0.w, acc[3]);
            acc[4] = fmaf(xv[j], w1.x, acc[4]);
            acc[5] = fmaf(xv[j], w1.y, acc[5]);
            acc[6] = fmaf(xv[j], w1.z, acc[6]);
            acc[7] = fmaf(xv[j], w1.w, acc[7]);
        }
    }
    #pragma unroll
    for (int o = 16; o; o >>= 1) {
        #pragma unroll
        for (int e = 0; e < EE; e++)
            acc[e] += __shfl_xor_sync(0xffffffffu, acc[e], o);
    }

    if (lane == 0) {
        float mx = acc[0];
        #pragma unroll
        for (int e = 1; e < EE; e++) mx = fmaxf(mx, acc[e]);
        float p[EE], se = 0.f;
        #pragma unroll
        for (int e = 0; e < EE; e++) { p[e] = expf(acc[e] - mx); se += p[e]; }
        const float inv = 1.f / se;
        #pragma unroll
        for (int e = 0; e < EE; e++) p[e] *= inv;
        int e0 = 0;
        #pragma unroll
        for (int e = 1; e < EE; e++) if (p[e] > p[e0]) e0 = e;
        int e1 = (e0 == 0) ? 1 : 0;
        #pragma unroll
        for (int e = 0; e < EE; e++) if (e != e0 && p[e] > p[e1]) e1 = e;
        const float z = expf(p[e1] - p[e0]);
        g_pw[2 * t]     = 1.f / (1.f + z);
        g_pw[2 * t + 1] = z / (1.f + z);
        int i0 = atomicAdd(&g_count[e0], 1);
        g_arows[e0 * NT + i0] = t;
        g_crows[e0 * NT + i0] = 2 * t;
        int i1 = atomicAdd(&g_count[e1], 1);
        g_arows[e1 * NT + i1] = t;
        g_crows[e1 * NT + i1] = 2 * t + 1;
    }
}

// expert prefix offset computed inline from g_count
__device__ __forceinline__ int expert_offset(int e) {
    int a = 0;
    #pragma unroll
    for (int i = 0; i < EE; i++) a += (i < e) ? g_count[i] : 0;
    return a;
}

// ---------------- fused gating+up fp16 GEMM (CTA 128x64, occ 2) --------------
// blockIdx.x in [0,32): GEMM n-tile; [32,48): one-shot Wd fp32->fp16 convert CTA.
__global__ __launch_bounds__(256, 2)
void moe_gu_kernel(const float* __restrict__ Wd) {
    const int tid = threadIdx.x;
    if (blockIdx.x >= GU_NT) {
        const int chunk = (blockIdx.x - GU_NT)
                        + GU_XCV * (blockIdx.y + 32 * blockIdx.z);
        cvt_chunk(Wd, g_Wdh, chunk, tid);
        return;
    }

    const int e = blockIdx.z;
    const int M = g_count[e];
    const int m0 = blockIdx.y * 128;
    if (m0 >= M) return;
    const int n0 = blockIdx.x * 64;

    extern __shared__ char sm[];
    const uint32_t smb = smem_u32(sm);
    const int wid = tid >> 5, lane = tid & 31;
    const int g = lane >> 2, t4 = lane & 3;
    const int wm = wid & 3, wn = wid >> 2;
    const int lrow = lane & 7, quad = lane >> 3;
    const int frow = ((quad & 1) << 3) + lrow;
    const int kgi = quad >> 1;
    const int ngq = quad >> 1;

    const int* arows = g_arows + e * NT;
    const __half* Bg = g_Wgh + (size_t)e * DD * FF;
    const __half* Bu = g_Wuh + (size_t)e * DD * FF;

    const __half* gA[2]; uint32_t sA[2];
    #pragma unroll
    for (int j = 0; j < 2; j++) {
        const int idx = tid + j * 256;
        const int r = idx >> 2, cg = idx & 3;
        gA[j] = g_Xh + (size_t)arows[min(m0 + r, M - 1)] * DD + cg * 8;
        sA[j] = a_smaddr(smb, r, cg);
    }
    const int b_k = tid >> 3, b_n = tid & 7;
    const __half* gG = Bg + (size_t)b_k * FF + n0 + b_n * 8;
    const __half* gU = Bu + (size_t)b_k * FF + n0 + b_n * 8;
    const uint32_t sG = b_smaddr64(smb + A_STG_B, b_k, b_n);
    const uint32_t sU = b_smaddr64(smb + A_STG_B + GU_B_STG, b_k, b_n);

    #pragma unroll
    for (int s = 0; s < NSTG - 1; s++) {
        const int kof = s * BKH;
        const uint32_t so = s * GU_STG;
        CP_ASYNC16(sA[0] + so, gA[0] + kof);
        CP_ASYNC16(sA[1] + so, gA[1] + kof);
        CP_ASYNC16(sG + so, gG + (size_t)kof * FF);
        CP_ASYNC16(sU + so, gU + (size_t)kof * FF);
        CP_COMMIT();
    }

    float accG[2][4][4], accU[2][4][4];
    #pragma unroll
    for (int i = 0; i < 2; i++)
        #pragma unroll
        for (int j = 0; j < 4; j++)
            #pragma unroll
            for (int q = 0; q < 4; q++) { accG[i][j][q] = 0.f; accU[i][j][q] = 0.f; }

    for (int kt = 0; kt < KT_GU; kt++) {
        CP_WAIT2();
        __syncthreads();
        {
            const int kn = kt + NSTG - 1;
            if (kn < KT_GU) {
                const int kof = kn * BKH;
                const uint32_t so = (kn & (NSTG - 1)) * GU_STG;
                CP_ASYNC16(sA[0] + so, gA[0] + kof);
                CP_ASYNC16(sA[1] + so, gA[1] + kof);
                CP_ASYNC16(sG + so, gG + (size_t)kof * FF);
                CP_ASYNC16(sU + so, gU + (size_t)kof * FF);
            }
            CP_COMMIT();
        }
        const uint32_t stA = smb + (kt & (NSTG - 1)) * GU_STG;
        const uint32_t stG = stA + A_STG_B;
        const uint32_t stU = stG + GU_B_STG;
        #pragma unroll
        for (int kk = 0; kk < 2; kk++) {
            uint32_t af[2][4];
            #pragma unroll
            for (int mf = 0; mf < 2; mf++) {
                const int r = wm * 32 + mf * 16 + frow;
                LDMX4(af[mf][0], af[mf][1], af[mf][2], af[mf][3],
                      a_smaddr(stA, r, kk * 2 + kgi));
            }
            uint32_t bg[2][4], bu[2][4];
            #pragma unroll
            for (int w16 = 0; w16 < 2; w16++) {
                const int k = kk * 16 + ((quad & 1) << 3) + lrow;
                const int ng = wn * 4 + w16 * 2 + ngq;
                LDMX4T(bg[w16][0], bg[w16][1], bg[w16][2], bg[w16][3],
                       b_smaddr64(stG, k, ng));
                LDMX4T(bu[w16][0], bu[w16][1], bu[w16][2], bu[w16][3],
                       b_smaddr64(stU, k, ng));
            }
            #pragma unroll
            for (int nf = 0; nf < 4; nf++) {
                const int w16 = nf >> 1, sl = (nf & 1) * 2;
                #pragma unroll
                for (int mf = 0; mf < 2; mf++) {
                    mma_f16(accG[mf][nf], af[mf], bg[w16][sl], bg[w16][sl + 1]);
                    mma_f16(accU[mf][nf], af[mf], bu[w16][sl], bu[w16][sl + 1]);
                }
            }
        }
    }

    const int hbase = expert_offset(e);
    const int* crows = g_crows + e * NT;
    #pragma unroll
    for (int mf = 0; mf < 2; mf++) {
        const int r_lo = m0 + wm * 32 + mf * 16 + g;
        const int r_hi = r_lo + 8;
        const bool v_lo = r_lo < M, v_hi = r_hi < M;
        const float pw_lo = v_lo ? g_pw[crows[r_lo]] : 0.f;
        const float pw_hi = v_hi ? g_pw[crows[r_hi]] : 0.f;
        __half* h_lo = g_Hh + (size_t)(hbase + (v_lo ? r_lo : 0)) * FF;
        __half* h_hi = g_Hh + (size_t)(hbase + (v_hi ? r_hi : 0)) * FF;
        #pragma unroll
        for (int nf = 0; nf < 4; nf++) {
            const int cc = n0 + wn * 32 + nf * 8 + t4 * 2;
            if (v_lo) {
                const float g0 = accG[mf][nf][0], u0 = accU[mf][nf][0];
                const float g1 = accG[mf][nf][1], u1 = accU[mf][nf][1];
                *(__half2*)(h_lo + cc) = __floats2half2_rn(
                    pw_lo * (g0 / (1.f + __expf(-g0))) * u0,
                    pw_lo * (g1 / (1.f + __expf(-g1))) * u1);
            }
            if (v_hi) {
                const float g0 = accG[mf][nf][2], u0 = accU[mf][nf][2];
                const float g1 = accG[mf][nf][3], u1 = accU[mf][nf][3];
                *(__half2*)(h_hi + cc) = __floats2half2_rn(
                    pw_hi * (g0 / (1.f + __expf(-g0))) * u0,
                    pw_hi * (g1 / (1.f + __expf(-g1))) * u1);
            }
        }
    }
}

// ---------------- down fp16 GEMM (CTA 128x128, occ 2) -------------------------
__global__ __launch_bounds__(256, 2)
void moe_dn_kernel(float* __restrict__ out) {
    const int e = blockIdx.z;
    const int M = g_count[e];
    const int m0 = blockIdx.y * 128;
    if (m0 >= M) return;
    const int n0 = blockIdx.x * 128;

    extern __shared__ char sm[];
    const uint32_t smb = smem_u32(sm);
    const int tid = threadIdx.x;
    const int wid = tid >> 5, lane = tid & 31;
    const int g = lane >> 2, t4 = lane & 3;
    const int wm = wid & 1, wn = wid >> 1;
    const int lrow = lane & 7, quad = lane >> 3;
    const int frow = ((quad & 1) << 3) + lrow;
    const int kgi = quad >> 1;
    const int ngq = quad >> 1;

    const __half* Bd = g_Wdh + (size_t)e * FF * DD;
    const int base_row = expert_offset(e) + m0;

    const __half* gA[2]; uint32_t sA[2];
    #pragma unroll
    for (int j = 0; j < 2; j++) {
        const int idx = tid + j * 256;
        const int r = idx >> 2, cg = idx & 3;
        gA[j] = g_Hh + (size_t)min(base_row + r, NP - 1) * FF + cg * 8;
        sA[j] = a_smaddr(smb, r, cg);
    }
    const __half* gB[2]; uint32_t sB[2];
    #pragma unroll
    for (int j = 0; j < 2; j++) {
        const int idx = tid + j * 256;
        const int k = idx >> 4, ng = idx & 15;
        gB[j] = Bd + (size_t)k * DD + n0 + ng * 8;
        sB[j] = b_smaddr(smb + A_STG_B, k, ng);
    }

    #pragma unroll
    for (int s = 0; s < NSTG - 1; s++) {
        const int kof = s * BKH;
        const uint32_t so = s * DN_STG;
        #pragma unroll
        for (int j = 0; j < 2; j++) {
            CP_ASYNC16(sA[j] + so, gA[j] + kof);
            CP_ASYNC16(sB[j] + so, gB[j] + (size_t)kof * DD);
        }
        CP_COMMIT();
    }

    float acc[4][4][4];
    #pragma unroll
    for (int i = 0; i < 4; i++)
        #pragma unroll
        for (int j = 0; j < 4; j++)
            #pragma unroll
            for (int q = 0; q < 4; q++) acc[i][j][q] = 0.f;

    for (int kt = 0; kt < KT_DN; kt++) {
        CP_WAIT2();
        __syncthreads();
        {
            const int kn = kt + NSTG - 1;
            if (kn < KT_DN) {
                const int kof = kn * BKH;
                const uint32_t so = (kn & (NSTG - 1)) * DN_STG;
                #pragma unroll
                for (int j = 0; j < 2; j++) {
                    CP_ASYNC16(sA[j] + so, gA[j] + kof);
                    CP_ASYNC16(sB[j] + so, gB[j] + (size_t)kof * DD);
                }
            }
            CP_COMMIT();
        }
        const uint32_t stA = smb + (kt & (NSTG - 1)) * DN_STG;
        const uint32_t stB = stA + A_STG_B;
        #pragma unroll
        for (int kk = 0; kk < 2; kk++) {
            uint32_t af[4][4];
            #pragma unroll
            for (int mf = 0; mf < 4; mf++) {
                const int r = wm * 64 + mf * 16 + frow;
                LDMX4(af[mf][0], af[mf][1], af[mf][2], af[mf][3],
                      a_smaddr(stA, r, kk * 2 + kgi));
            }
            uint32_t bb[2][4];
            #pragma unroll
            for (int w16 = 0; w16 < 2; w16++) {
                const int k = kk * 16 + ((quad & 1) << 3) + lrow;
                const int ng = wn * 4 + w16 * 2 + ngq;
                LDMX4T(bb[w16][0], bb[w16][1], bb[w16][2], bb[w16][3],
                       b_smaddr(stB, k, ng));
            }
            #pragma unroll
            for (int nf = 0; nf < 4; nf++) {
                const int w16 = nf >> 1, sl = (nf & 1) * 2;
                #pragma unroll
                for (int mf = 0; mf < 4; mf++)
                    mma_f16(acc[mf][nf], af[mf], bb[w16][sl], bb[w16][sl + 1]);
            }
        }
    }

    const int* crows = g_crows + e * NT;
    #pragma unroll
    for (int mf = 0; mf < 4; mf++) {
        const int r_lo = m0 + wm * 64 + mf * 16 + g;
        const int r_hi = r_lo + 8;
        float* o_lo = (r_lo < M) ? (out + (size_t)(crows[r_lo] >> 1) * DD) : nullptr;
        float* o_hi = (r_hi < M) ? (out + (size_t)(crows[r_hi] >> 1) * DD) : nullptr;
        #pragma unroll
        for (int nf = 0; nf < 4; nf++) {
            const int cc = n0 + wn * 32 + nf * 8 + t4 * 2;
            if (o_lo) {
                atomicAdd(o_lo + cc,     acc[mf][nf][0]);
                atomicAdd(o_lo + cc + 1, acc[mf][nf][1]);
            }
            if (o_hi) {
                atomicAdd(o_hi + cc,     acc[mf][nf][2]);
                atomicAdd(o_hi + cc + 1, acc[mf][nf][3]);
            }
        }
    }
}

// ---------------- launcher ---------------------------------------------------
extern "C" void kernel_launch(void* const* d_in, const int* in_sizes, int n_in,
                              void* d_out, int out_size) {
    const float* x  = (const float*)d_in[0];
    const float* Wr = (const float*)d_in[1];
    const float* Wg = (const float*)d_in[2];
    const float* Wu = (const float*)d_in[3];
    const float* Wd = (const float*)d_in[4];
    float* out = (float*)d_out;

    cudaFuncSetAttribute(moe_gu_kernel, cudaFuncAttributeMaxDynamicSharedMemorySize, GU_SMEM);
    cudaFuncSetAttribute(moe_dn_kernel, cudaFuncAttributeMaxDynamicSharedMemorySize, DN_SMEM);

    // g_count is zero at first call (static zero-init); re-zeroed after DN below,
    // so every invocation starts with zeroed counts (graph-replay safe).
    prep_kernel<<<RTR_BLKS + 2 * CVT_BLKS, 256>>>(x, Wr, Wg, Wu, out);
    moe_gu_kernel<<<dim3(GU_NT + GU_XCV, 32, EE), 256, GU_SMEM>>>(Wd);
    moe_dn_kernel<<<dim3(DD / 128, 32, EE), 256, DN_SMEM>>>(out);

    int* cnt;
    cudaGetSymbolAddress((void**)&cnt, g_count);
    cudaMemsetAsync(cnt, 0, EE * sizeof(int));
}